// round 7
// baseline (speedup 1.0000x reference)
#include <cuda_runtime.h>
#include <cuda_fp16.h>
#include <cstdint>

// ---------------------------------------------------------------------------
// MultiScaleTimeMixer via warp-level HMMA (mma.sync m16n8k16 fp16, fp32 acc).
// 3-pass fp16 hi/lo split for ~fp32 accuracy. B=2048, T=128, C=128.
// ---------------------------------------------------------------------------

#define NB 2048

// ---- fp32 intermediates ----
__device__ float g_mu[NB];
__device__ float g_rs[NB];
__device__ float g_t0[(long long)NB * 128 * 128];
__device__ float g_g1[(long long)NB * 128 * 64];
__device__ float g_u1[(long long)NB * 128 * 64];
__device__ float g_g2[(long long)NB * 128 * 32];
__device__ float g_u2[(long long)NB * 128 * 32];

// ---- fp16 hi/lo weights, [N][K] row-major (K-major for B^T) ----
__device__ __align__(16) __half g_B0ah[16384], g_B0al[16384];
__device__ __align__(16) __half g_B0bh[16384], g_B0bl[16384];
__device__ __align__(16) __half g_B1ah[4096],  g_B1al[4096];
__device__ __align__(16) __half g_B1bh[4096],  g_B1bl[4096];
__device__ __align__(16) __half g_B2ah[1024],  g_B2al[1024];
__device__ __align__(16) __half g_B2bh[1024],  g_B2bl[1024];
__device__ __align__(16) __half g_Bc1h[128*256], g_Bc1l[128*256];
__device__ __align__(16) __half g_Bc2h[128*512], g_Bc2l[128*512];

__device__ __forceinline__ uint32_t smem_u32(const void* p) {
    uint32_t a;
    asm("{ .reg .u64 t; cvta.to.shared.u64 t, %1; cvt.u32.u64 %0, t; }"
        : "=r"(a) : "l"(p));
    return a;
}

#define LDSM4(r, addr)                                                          \
    asm volatile("ldmatrix.sync.aligned.m8n8.x4.shared.b16 {%0,%1,%2,%3}, [%4];" \
        : "=r"((r)[0]), "=r"((r)[1]), "=r"((r)[2]), "=r"((r)[3]) : "r"(addr))

#define MMA16816(d, a, b0, b1)                                                  \
    asm volatile("mma.sync.aligned.m16n8k16.row.col.f32.f16.f16.f32 "           \
        "{%0,%1,%2,%3}, {%4,%5,%6,%7}, {%8,%9}, {%0,%1,%2,%3};"                 \
        : "+f"((d)[0]), "+f"((d)[1]), "+f"((d)[2]), "+f"((d)[3])                 \
        : "r"((a)[0]), "r"((a)[1]), "r"((a)[2]), "r"((a)[3]), "r"(b0), "r"(b1))

__device__ __forceinline__ uint32_t pack2h(__half a, __half b) {
    return (uint32_t)__half_as_ushort(a) | ((uint32_t)__half_as_ushort(b) << 16);
}
__device__ __forceinline__ void hsplit(float v, __half& h, __half& l) {
    h = __float2half_rn(v);
    l = __float2half_rn(v - __half2float(h));
}
__device__ __forceinline__ float hswish(float v) {
    return v * fminf(fmaxf(v + 3.f, 0.f), 6.f) * (1.f / 6.f);
}

// ---------------------------------------------------------------------------
// Per-batch LayerNorm stats
// ---------------------------------------------------------------------------
__global__ void stats_k(const float* __restrict__ x) {
    int b = blockIdx.x;
    const float4* xp = (const float4*)(x + (long long)b * 16384);
    float s = 0.f, q = 0.f;
    for (int i = threadIdx.x; i < 4096; i += 256) {
        float4 v = xp[i];
        s += v.x + v.y + v.z + v.w;
        q += v.x * v.x + v.y * v.y + v.z * v.z + v.w * v.w;
    }
    #pragma unroll
    for (int o = 16; o > 0; o >>= 1) {
        s += __shfl_down_sync(0xffffffffu, s, o);
        q += __shfl_down_sync(0xffffffffu, q, o);
    }
    __shared__ float ss[8], qs[8];
    int w = threadIdx.x >> 5, l = threadIdx.x & 31;
    if (l == 0) { ss[w] = s; qs[w] = q; }
    __syncthreads();
    if (threadIdx.x == 0) {
        float S = 0.f, Q = 0.f;
        #pragma unroll
        for (int i = 0; i < 8; i++) { S += ss[i]; Q += qs[i]; }
        float mu = S * (1.f / 16384.f);
        float var = Q * (1.f / 16384.f) - mu * mu;
        g_mu[b] = mu;
        g_rs[b] = rsqrtf(var + 1e-5f);
    }
}

// ---------------------------------------------------------------------------
// Weight prep: tril mask + fp16 hi/lo split; conv weights -> [co][tt*128+c]
// ---------------------------------------------------------------------------
__global__ void prep_k(const float* __restrict__ W0a, const float* __restrict__ W0b,
                       const float* __restrict__ W1a, const float* __restrict__ W1b,
                       const float* __restrict__ W2a, const float* __restrict__ W2b,
                       const float* __restrict__ c1w, const float* __restrict__ c2w) {
    int tid = blockIdx.x * blockDim.x + threadIdx.x;
    int stride = gridDim.x * blockDim.x;
    for (int i = tid; i < 16384; i += stride) {
        int n = i >> 7, k = i & 127;
        float m = (k <= n) ? 1.f : 0.f;
        hsplit(m * W0a[i], g_B0ah[i], g_B0al[i]);
        hsplit(m * W0b[i], g_B0bh[i], g_B0bl[i]);
    }
    for (int i = tid; i < 4096; i += stride) {
        int n = i >> 6, k = i & 63;
        float m = (k <= n) ? 1.f : 0.f;
        hsplit(m * W1a[i], g_B1ah[i], g_B1al[i]);
        hsplit(m * W1b[i], g_B1bh[i], g_B1bl[i]);
    }
    for (int i = tid; i < 1024; i += stride) {
        int n = i >> 5, k = i & 31;
        float m = (k <= n) ? 1.f : 0.f;
        hsplit(m * W2a[i], g_B2ah[i], g_B2al[i]);
        hsplit(m * W2b[i], g_B2bh[i], g_B2bl[i]);
    }
    for (int i = tid; i < 128 * 256; i += stride) {
        int co = i >> 8, k = i & 255;
        int tt = k >> 7, c = k & 127;
        hsplit(c1w[co * 256 + c * 2 + tt], g_Bc1h[i], g_Bc1l[i]);
    }
    for (int i = tid; i < 128 * 512; i += stride) {
        int co = i >> 9, k = i & 511;
        int tt = k >> 7, c = k & 127;
        hsplit(c2w[co * 512 + c * 4 + tt], g_Bc2h[i], g_Bc2l[i]);
    }
}

// ---------------------------------------------------------------------------
// HMMA GEMM: D[128-row tile, N] = A[M,KTOT] @ B^T, B stored [N][KTOT] fp16
// hi/lo. 3-pass: Ah*Bh + Ah*Bl + Al*Bh. fp32 accum.
//   NORM: LayerNorm folded into A load (stage 0a).
//   mode 0: out[row*N + col]
//   mode 1: out[(row>>rbsh)*S0 + (row & mask) + col*S2 + offs], via smem
//           transpose tile for coalesced stores.
// ---------------------------------------------------------------------------
template<int N, int KTOT, bool NORM>
__global__ __launch_bounds__(256)
void hgemm_k(const float* __restrict__ A,
             const __half* __restrict__ Bh,
             const __half* __restrict__ Bl,
             const float* __restrict__ bias,
             float* __restrict__ out,
             int hsw, int mode, int rbsh, int S0, int S2, int offs,
             const float* __restrict__ gamma, const float* __restrict__ beta) {
    constexpr int NCHUNK = (KTOT + 63) / 64;
    constexpr int NG16 = N / 16;
    constexpr int SA = 72;                 // half-stride per row (144B)
    constexpr int ABYTES = 128 * SA * 2;   // 18432
    constexpr int BBYTES = N * SA * 2;

    extern __shared__ char dsm[];
    __shared__ float s_bias[N];

    const int tid = threadIdx.x;
    const int wid = tid >> 5, lane = tid & 31;
    const int r0 = wid * 16;
    const long long row0 = (long long)blockIdx.x * 128;

    char* pAh = dsm;
    char* pAl = dsm + ABYTES;
    char* pBh = dsm + 2 * ABYTES;
    char* pBl = pBh + BBYTES;
    const uint32_t uAh = smem_u32(pAh);
    const uint32_t uAl = uAh + ABYTES;
    const uint32_t uBh = uAh + 2 * ABYTES;
    const uint32_t uBl = uBh + BBYTES;

    if (tid < N) s_bias[tid] = bias[tid];

    // per-thread ldmatrix base offsets (bytes)
    const uint32_t aOff =
        (uint32_t)((r0 + ((lane >> 3) & 1) * 8 + (lane & 7)) * SA + (lane >> 4) * 8) * 2;
    const uint32_t bOff =
        (uint32_t)(((lane >> 4) * 8 + (lane & 7)) * SA + ((lane >> 3) & 1) * 8) * 2;

    float acc[NG16 * 2][4];
    #pragma unroll
    for (int i = 0; i < NG16 * 2; i++)
        #pragma unroll
        for (int j = 0; j < 4; j++) acc[i][j] = 0.f;

    for (int c = 0; c < NCHUNK; c++) {
        const int k0 = c * 64;
        // ---- stage A: 128 x 64 fp32 -> fp16 hi/lo ----
        #pragma unroll
        for (int qq = 0; qq < 8; qq++) {
            int q = qq * 256 + tid;
            int r = q >> 4, kq = q & 15;
            int col = k0 + kq * 4;
            float4 v = make_float4(0.f, 0.f, 0.f, 0.f);
            if (KTOT >= 64 || col < KTOT)
                v = *(const float4*)(A + (row0 + r) * KTOT + col);
            if (NORM) {
                long long grow = row0 + r;
                int b = (int)(grow >> 7);
                float mu = g_mu[b], rs = g_rs[b];
                int t = (int)(grow & 127);
                float4 g  = *(const float4*)(gamma + t * 128 + col);
                float4 be = *(const float4*)(beta + t * 128 + col);
                v.x = (v.x - mu) * rs * g.x + be.x;
                v.y = (v.y - mu) * rs * g.y + be.y;
                v.z = (v.z - mu) * rs * g.z + be.z;
                v.w = (v.w - mu) * rs * g.w + be.w;
            }
            __half hx, hy, hz, hw, lx, ly, lz, lw;
            hsplit(v.x, hx, lx); hsplit(v.y, hy, ly);
            hsplit(v.z, hz, lz); hsplit(v.w, hw, lw);
            uint32_t off = (uint32_t)(r * SA + kq * 4) * 2;
            uint2 uh; uh.x = pack2h(hx, hy); uh.y = pack2h(hz, hw);
            uint2 ul; ul.x = pack2h(lx, ly); ul.y = pack2h(lz, lw);
            *(uint2*)(pAh + off) = uh;
            *(uint2*)(pAl + off) = ul;
        }
        // ---- stage B hi/lo: N x 64 fp16 copy ----
        #pragma unroll
        for (int qq = 0; qq < N / 32; qq++) {
            int q = qq * 256 + tid;
            int n = q >> 3, kq = q & 7;
            int col = k0 + kq * 8;
            uint4 vh = make_uint4(0, 0, 0, 0), vl = make_uint4(0, 0, 0, 0);
            if (KTOT >= 64 || col < KTOT) {
                vh = *(const uint4*)(Bh + n * KTOT + col);
                vl = *(const uint4*)(Bl + n * KTOT + col);
            }
            uint32_t off = (uint32_t)(n * SA + kq * 8) * 2;
            *(uint4*)(pBh + off) = vh;
            *(uint4*)(pBl + off) = vl;
        }
        __syncthreads();
        // ---- compute: 4 k16 steps ----
        #pragma unroll
        for (int kk = 0; kk < 4; kk++) {
            uint32_t ah[4], al[4];
            LDSM4(ah, uAh + aOff + kk * 32);
            LDSM4(al, uAl + aOff + kk * 32);
            #pragma unroll
            for (int g = 0; g < NG16; g++) {
                uint32_t bh[4], bl[4];
                LDSM4(bh, uBh + bOff + g * (16 * SA * 2) + kk * 32);
                MMA16816(acc[g * 2 + 0], ah, bh[0], bh[1]);
                MMA16816(acc[g * 2 + 1], ah, bh[2], bh[3]);
                MMA16816(acc[g * 2 + 0], al, bh[0], bh[1]);
                MMA16816(acc[g * 2 + 1], al, bh[2], bh[3]);
                LDSM4(bl, uBl + bOff + g * (16 * SA * 2) + kk * 32);
                MMA16816(acc[g * 2 + 0], ah, bl[0], bl[1]);
                MMA16816(acc[g * 2 + 1], ah, bl[2], bl[3]);
            }
        }
        __syncthreads();
    }

    // ---- epilogue ----
    const int cbase = 2 * (lane & 3);
    const int ra = r0 + (lane >> 2);
    if (mode == 0) {
        #pragma unroll
        for (int g = 0; g < NG16; g++) {
            #pragma unroll
            for (int j = 0; j < 2; j++) {
                int cc = g * 16 + j * 8 + cbase;
                float b0 = s_bias[cc], b1 = s_bias[cc + 1];
                float* ac = acc[g * 2 + j];
                float v0 = ac[0] + b0, v1 = ac[1] + b1;
                float v2 = ac[2] + b0, v3 = ac[3] + b1;
                if (hsw) { v0 = hswish(v0); v1 = hswish(v1); v2 = hswish(v2); v3 = hswish(v3); }
                *(float2*)(out + (row0 + ra) * N + cc) = make_float2(v0, v1);
                *(float2*)(out + (row0 + ra + 8) * N + cc) = make_float2(v2, v3);
            }
        }
    } else {
        // transpose through smem for coalesced scatter
        float* tile = (float*)dsm;
        const int ts = N + 1;
        #pragma unroll
        for (int g = 0; g < NG16; g++) {
            #pragma unroll
            for (int j = 0; j < 2; j++) {
                int cc = g * 16 + j * 8 + cbase;
                float b0 = s_bias[cc], b1 = s_bias[cc + 1];
                float* ac = acc[g * 2 + j];
                float v0 = ac[0] + b0, v1 = ac[1] + b1;
                float v2 = ac[2] + b0, v3 = ac[3] + b1;
                if (hsw) { v0 = hswish(v0); v1 = hswish(v1); v2 = hswish(v2); v3 = hswish(v3); }
                tile[ra * ts + cc] = v0;
                tile[ra * ts + cc + 1] = v1;
                tile[(ra + 8) * ts + cc] = v2;
                tile[(ra + 8) * ts + cc + 1] = v3;
            }
        }
        __syncthreads();
        const int mask = (1 << rbsh) - 1;
        #pragma unroll
        for (int it = 0; it < N / 2; it++) {
            int q = it * 256 + tid;
            int rr = q & 127, cc = q >> 7;
            float v = tile[rr * ts + cc];
            long long grow = row0 + rr;
            long long qb = grow >> rbsh;
            int rrem = (int)(grow & mask);
            out[qb * (long long)S0 + rrem + (long long)cc * S2 + offs] = v;
        }
    }
}

// ---------------------------------------------------------------------------
extern "C" void kernel_launch(void* const* d_in, const int* in_sizes, int n_in,
                              void* d_out, int out_size) {
    const float* x   = (const float*)d_in[0];
    const float* lg  = (const float*)d_in[1];
    const float* lb  = (const float*)d_in[2];
    const float* W0a = (const float*)d_in[3];
    const float* b0a = (const float*)d_in[4];
    const float* W0b = (const float*)d_in[5];
    const float* b0b = (const float*)d_in[6];
    const float* c1w = (const float*)d_in[7];
    const float* c1b = (const float*)d_in[8];
    const float* W1a = (const float*)d_in[9];
    const float* b1a = (const float*)d_in[10];
    const float* W1b = (const float*)d_in[11];
    const float* b1b = (const float*)d_in[12];
    const float* c2w = (const float*)d_in[13];
    const float* c2b = (const float*)d_in[14];
    const float* W2a = (const float*)d_in[15];
    const float* b2a = (const float*)d_in[16];
    const float* W2b = (const float*)d_in[17];
    const float* b2b = (const float*)d_in[18];
    float* out = (float*)d_out;

    float *pt0, *pg1, *pu1, *pg2, *pu2;
    __half *p0ah, *p0al, *p0bh, *p0bl, *p1ah, *p1al, *p1bh, *p1bl;
    __half *p2ah, *p2al, *p2bh, *p2bl, *pc1h, *pc1l, *pc2h, *pc2l;
    cudaGetSymbolAddress((void**)&pt0, g_t0);
    cudaGetSymbolAddress((void**)&pg1, g_g1);
    cudaGetSymbolAddress((void**)&pu1, g_u1);
    cudaGetSymbolAddress((void**)&pg2, g_g2);
    cudaGetSymbolAddress((void**)&pu2, g_u2);
    cudaGetSymbolAddress((void**)&p0ah, g_B0ah); cudaGetSymbolAddress((void**)&p0al, g_B0al);
    cudaGetSymbolAddress((void**)&p0bh, g_B0bh); cudaGetSymbolAddress((void**)&p0bl, g_B0bl);
    cudaGetSymbolAddress((void**)&p1ah, g_B1ah); cudaGetSymbolAddress((void**)&p1al, g_B1al);
    cudaGetSymbolAddress((void**)&p1bh, g_B1bh); cudaGetSymbolAddress((void**)&p1bl, g_B1bl);
    cudaGetSymbolAddress((void**)&p2ah, g_B2ah); cudaGetSymbolAddress((void**)&p2al, g_B2al);
    cudaGetSymbolAddress((void**)&p2bh, g_B2bh); cudaGetSymbolAddress((void**)&p2bl, g_B2bl);
    cudaGetSymbolAddress((void**)&pc1h, g_Bc1h); cudaGetSymbolAddress((void**)&pc1l, g_Bc1l);
    cudaGetSymbolAddress((void**)&pc2h, g_Bc2h); cudaGetSymbolAddress((void**)&pc2l, g_Bc2l);

    // dynamic smem: mainloop = 2*18432 + 2*N*144; epilogue tile = 128*(N+1)*4
    const int ds128 = 2 * 18432 + 2 * 128 * 144;  // 73728 (tile 66048 fits)
    const int ds64  = 2 * 18432 + 2 * 64 * 144;   // 55296 (tile 33280 fits)
    const int ds32  = 2 * 18432 + 2 * 32 * 144;   // 46080 (tile 16896 fits)
    cudaFuncSetAttribute(hgemm_k<128, 128, true>,
                         cudaFuncAttributeMaxDynamicSharedMemorySize, ds128);
    cudaFuncSetAttribute(hgemm_k<128, 128, false>,
                         cudaFuncAttributeMaxDynamicSharedMemorySize, ds128);
    cudaFuncSetAttribute(hgemm_k<128, 256, false>,
                         cudaFuncAttributeMaxDynamicSharedMemorySize, ds128);
    cudaFuncSetAttribute(hgemm_k<128, 512, false>,
                         cudaFuncAttributeMaxDynamicSharedMemorySize, ds128);
    cudaFuncSetAttribute(hgemm_k<64, 64, false>,
                         cudaFuncAttributeMaxDynamicSharedMemorySize, ds64);
    cudaFuncSetAttribute(hgemm_k<32, 32, false>,
                         cudaFuncAttributeMaxDynamicSharedMemorySize, ds32);

    stats_k<<<NB, 256>>>(x);
    prep_k<<<128, 256>>>(W0a, W0b, W1a, W1b, W2a, W2b, c1w, c2w);

    // scale 0: hsw(LN(x) @ W0a^T + b0a) -> t0 (row-major)
    hgemm_k<128, 128, true><<<2048, 256, ds128>>>(
        x, p0ah, p0al, b0a, pt0, 1, 0, 0, 0, 0, 0, lg, lb);
    // t0 @ W0b^T + b0b -> out[b, j, t], rows 0..127
    hgemm_k<128, 128, false><<<2048, 256, ds128>>>(
        pt0, p0bh, p0bl, b0b, out, 0, 1, 7, 28672, 128, 0, nullptr, nullptr);

    // conv1 (reshape GEMM, K=256) -> g1[b, co, s]
    hgemm_k<128, 256, false><<<1024, 256, ds128>>>(
        x, pc1h, pc1l, c1b, pg1, 0, 1, 6, 8192, 64, 0, nullptr, nullptr);
    // triu1a + hsw -> u1 row-major
    hgemm_k<64, 64, false><<<2048, 256, ds64>>>(
        pg1, p1ah, p1al, b1a, pu1, 1, 0, 0, 0, 0, 0, nullptr, nullptr);
    // triu1b -> out[b, 128+s, co], rows 128..191
    hgemm_k<64, 64, false><<<2048, 256, ds64>>>(
        pu1, p1bh, p1bl, b1b, out, 0, 1, 7, 28672, 128, 16384, nullptr, nullptr);

    // conv2 (K=512) -> g2[b, co, s]
    hgemm_k<128, 512, false><<<512, 256, ds128>>>(
        x, pc2h, pc2l, c2b, pg2, 0, 1, 5, 4096, 32, 0, nullptr, nullptr);
    // triu2a + hsw -> u2
    hgemm_k<32, 32, false><<<2048, 256, ds32>>>(
        pg2, p2ah, p2al, b2a, pu2, 1, 0, 0, 0, 0, 0, nullptr, nullptr);
    // triu2b -> out[b, 192+s, co], rows 192..223
    hgemm_k<32, 32, false><<<2048, 256, ds32>>>(
        pu2, p2bh, p2bl, b2b, out, 0, 1, 7, 28672, 128, 24576, nullptr, nullptr);
}

// round 9
// speedup vs baseline: 1.2760x; 1.2760x over previous
#include <cuda_runtime.h>
#include <cuda_fp16.h>
#include <cstdint>

// MultiScaleTimeMixer, fused per scale. HMMA fp16 hi/lo 3-pass, fp32 acc.

__device__ __align__(16) __half g_B0ah[16384], g_B0al[16384];
__device__ __align__(16) __half g_B0bh[16384], g_B0bl[16384];
__device__ __align__(16) __half g_B1ah[4096],  g_B1al[4096];
__device__ __align__(16) __half g_B1bh[4096],  g_B1bl[4096];
__device__ __align__(16) __half g_B2ah[1024],  g_B2al[1024];
__device__ __align__(16) __half g_B2bh[1024],  g_B2bl[1024];
__device__ __align__(16) __half g_Bc1h[128*256], g_Bc1l[128*256];
__device__ __align__(16) __half g_Bc2h[128*512], g_Bc2l[128*512];

__device__ __forceinline__ uint32_t smem_u32(const void* p) {
    uint32_t a;
    asm("{ .reg .u64 t; cvta.to.shared.u64 t, %1; cvt.u32.u64 %0, t; }" : "=r"(a) : "l"(p));
    return a;
}
#define LDSM4(r, addr)                                                           \
    asm volatile("ldmatrix.sync.aligned.m8n8.x4.shared.b16 {%0,%1,%2,%3}, [%4];" \
        : "=r"((r)[0]), "=r"((r)[1]), "=r"((r)[2]), "=r"((r)[3]) : "r"(addr))
#define MMA16816(d, a, b0, b1)                                                   \
    asm volatile("mma.sync.aligned.m16n8k16.row.col.f32.f16.f16.f32 "            \
        "{%0,%1,%2,%3}, {%4,%5,%6,%7}, {%8,%9}, {%0,%1,%2,%3};"                  \
        : "+f"((d)[0]), "+f"((d)[1]), "+f"((d)[2]), "+f"((d)[3])                  \
        : "r"((a)[0]), "r"((a)[1]), "r"((a)[2]), "r"((a)[3]), "r"(b0), "r"(b1))

__device__ __forceinline__ uint32_t pack2h(__half a, __half b) {
    return (uint32_t)__half_as_ushort(a) | ((uint32_t)__half_as_ushort(b) << 16);
}
__device__ __forceinline__ void hsplit(float v, __half& h, __half& l) {
    h = __float2half_rn(v); l = __float2half_rn(v - __half2float(h));
}
__device__ __forceinline__ float hswish(float v) {
    return v * fminf(fmaxf(v + 3.f, 0.f), 6.f) * (1.f / 6.f);
}
__device__ __forceinline__ void store_h(char* pH, char* pL, int idx, float v) {
    __half h, l; hsplit(v, h, l);
    *(__half*)(pH + idx * 2) = h; *(__half*)(pL + idx * 2) = l;
}

__global__ void prep_k(const float* __restrict__ W0a, const float* __restrict__ W0b,
                       const float* __restrict__ W1a, const float* __restrict__ W1b,
                       const float* __restrict__ W2a, const float* __restrict__ W2b,
                       const float* __restrict__ c1w, const float* __restrict__ c2w) {
    int tid = blockIdx.x * blockDim.x + threadIdx.x, st = gridDim.x * blockDim.x;
    for (int i = tid; i < 16384; i += st) {
        int n = i >> 7, k = i & 127; float m = (k <= n) ? 1.f : 0.f;
        hsplit(m * W0a[i], g_B0ah[i], g_B0al[i]);
        hsplit(m * W0b[i], g_B0bh[i], g_B0bl[i]);
    }
    for (int i = tid; i < 4096; i += st) {
        int n = i >> 6, k = i & 63; float m = (k <= n) ? 1.f : 0.f;
        hsplit(m * W1a[i], g_B1ah[i], g_B1al[i]);
        hsplit(m * W1b[i], g_B1bh[i], g_B1bl[i]);
    }
    for (int i = tid; i < 1024; i += st) {
        int n = i >> 5, k = i & 31; float m = (k <= n) ? 1.f : 0.f;
        hsplit(m * W2a[i], g_B2ah[i], g_B2al[i]);
        hsplit(m * W2b[i], g_B2bh[i], g_B2bl[i]);
    }
    for (int i = tid; i < 128 * 256; i += st) {
        int co = i >> 8, k = i & 255;
        hsplit(c1w[co * 256 + (k & 127) * 2 + (k >> 7)], g_Bc1h[i], g_Bc1l[i]);
    }
    for (int i = tid; i < 128 * 512; i += st) {
        int co = i >> 9, k = i & 511;
        hsplit(c2w[co * 512 + (k & 127) * 4 + (k >> 7)], g_Bc2h[i], g_Bc2l[i]);
    }
}

template<int NROWS, int KCH, int SBH>
__device__ __forceinline__ void load_b(char* pBh, char* pBl,
    const __half* __restrict__ gh, const __half* __restrict__ gl,
    int ktot, int kbase, int tid) {
    constexpr int PER = KCH / 8, TOT = NROWS * PER;
    for (int i = tid; i < TOT; i += 256) {
        int n = i / PER, kq = i % PER;
        uint32_t off = (uint32_t)(n * SBH + kq * 8) * 2;
        *(uint4*)(pBh + off) = *(const uint4*)(gh + n * ktot + kbase + kq * 8);
        *(uint4*)(pBl + off) = *(const uint4*)(gl + n * ktot + kbase + kq * 8);
    }
}

// 3-pass MMA over KS k16-steps. A resident (stride SAH halves, indexed by
// ksg = ks0+kk); B holds ONLY the current chunk (stride SBH, indexed by kk).
// Warp covers RB 16-row blocks x NG col groups gg=g*WC+wcp. TRI: skip ksg>gg.
template<int KS, int RB, int NG, int WC, int SAH, int SBH, bool TRI>
__device__ __forceinline__ void mma_chunk(uint32_t uAh, uint32_t uAl,
    uint32_t uBh, uint32_t uBl, uint32_t aoff, uint32_t boff,
    int wcp, int ks0, float (*acc)[4]) {
#pragma unroll
    for (int kk = 0; kk < KS; kk++) {
        int ksg = ks0 + kk;
        uint32_t ah[RB][4], al[RB][4];
        if (!TRI || ksg <= (NG - 1) * WC + wcp) {
#pragma unroll
            for (int rb = 0; rb < RB; rb++) {
                LDSM4(ah[rb], uAh + aoff + rb * (16 * SAH * 2) + (uint32_t)ksg * 32);
                LDSM4(al[rb], uAl + aoff + rb * (16 * SAH * 2) + (uint32_t)ksg * 32);
            }
        }
#pragma unroll
        for (int g = 0; g < NG; g++) {
            int gg = g * WC + wcp;
            if (TRI && ksg > gg) continue;
            uint32_t bh[4], bl[4];
            LDSM4(bh, uBh + boff + (uint32_t)(gg * (16 * SBH * 2) + kk * 32));
            LDSM4(bl, uBl + boff + (uint32_t)(gg * (16 * SBH * 2) + kk * 32));
#pragma unroll
            for (int rb = 0; rb < RB; rb++) {
                float* a0 = acc[(rb * NG + g) * 2]; float* a1 = acc[(rb * NG + g) * 2 + 1];
                MMA16816(a0, ah[rb], bh[0], bh[1]); MMA16816(a1, ah[rb], bh[2], bh[3]);
                MMA16816(a0, al[rb], bh[0], bh[1]); MMA16816(a1, al[rb], bh[2], bh[3]);
                MMA16816(a0, ah[rb], bl[0], bl[1]); MMA16816(a1, ah[rb], bl[2], bl[3]);
            }
        }
    }
}

template<int NA> __device__ __forceinline__ void zacc(float (*acc)[4]) {
#pragma unroll
    for (int i = 0; i < NA; i++) { acc[i][0] = acc[i][1] = acc[i][2] = acc[i][3] = 0.f; }
}

template<int RB, int NG, int WC, bool HSW, class F>
__device__ __forceinline__ void epi(float (*acc)[4], const float* sb,
                                    int r0, int wcp, int lane, F f) {
#pragma unroll
    for (int rb = 0; rb < RB; rb++)
#pragma unroll
    for (int g = 0; g < NG; g++)
#pragma unroll
    for (int j = 0; j < 2; j++) {
        const float* a = acc[(rb * NG + g) * 2 + j];
        int cc = (g * WC + wcp) * 16 + j * 8 + 2 * (lane & 3);
        int r = r0 + rb * 16 + (lane >> 2);
        float b0 = sb[cc], b1 = sb[cc + 1];
        float v0 = a[0] + b0, v1 = a[1] + b1, v2 = a[2] + b0, v3 = a[3] + b1;
        if (HSW) { v0 = hswish(v0); v1 = hswish(v1); v2 = hswish(v2); v3 = hswish(v3); }
        f(r, cc, v0); f(r, cc + 1, v1); f(r + 8, cc, v2); f(r + 8, cc + 1, v3);
    }
}

// ---------------- K0: LN + TriU(W0a) + hsw + TriU(W0b) -> out[b,j,t] --------
__global__ __launch_bounds__(256, 2)
void k0_kernel(const float* __restrict__ x, const float* __restrict__ lg,
               const float* __restrict__ lb, const float* __restrict__ b0a,
               const float* __restrict__ b0b, float* __restrict__ out) {
    extern __shared__ char dsm[];
    __shared__ float s_s[8], s_q[8], s_ms[2], s_b1[128], s_b2[128];
    const int tid = threadIdx.x, lane = tid & 31, wid = tid >> 5;
    const int wcp = wid >> 2, r0 = (wid & 3) * 32, b = blockIdx.x;
    char* pAh = dsm; char* pAl = dsm + 34816;
    char* pBh = dsm + 69632; char* pBl = dsm + 88064;
    const uint32_t uA = smem_u32(dsm);
    const uint32_t uAh = uA, uAl = uA + 34816, uBh = uA + 69632, uBl = uA + 88064;
    const uint32_t aoff = ((r0 + ((lane >> 3) & 1) * 8 + (lane & 7)) * 136 + (lane >> 4) * 8) * 2;
    const uint32_t boff = (((lane >> 4) * 8 + (lane & 7)) * 72 + ((lane >> 3) & 1) * 8) * 2;
    if (tid < 128) { s_b1[tid] = b0a[tid]; s_b2[tid] = b0b[tid]; }

    const float4* xb = (const float4*)(x + (long long)b * 16384);
    float sm = 0.f, sq = 0.f;
#pragma unroll
    for (int q = 0; q < 16; q++) {
        float4 v = xb[q * 256 + tid];
        sm += v.x + v.y + v.z + v.w;
        sq += v.x * v.x + v.y * v.y + v.z * v.z + v.w * v.w;
    }
#pragma unroll
    for (int o = 16; o > 0; o >>= 1) {
        sm += __shfl_down_sync(~0u, sm, o); sq += __shfl_down_sync(~0u, sq, o);
    }
    if (lane == 0) { s_s[wid] = sm; s_q[wid] = sq; }
    __syncthreads();
    if (tid == 0) {
        float S = 0.f, Q = 0.f;
#pragma unroll
        for (int i = 0; i < 8; i++) { S += s_s[i]; Q += s_q[i]; }
        float mu = S * (1.f / 16384.f);
        s_ms[0] = mu; s_ms[1] = rsqrtf(Q * (1.f / 16384.f) - mu * mu + 1e-5f);
    }
    __syncthreads();
    const float mu = s_ms[0], rs = s_ms[1];
#pragma unroll
    for (int qq = 0; qq < 16; qq++) {
        int q = qq * 256 + tid;
        int r = q >> 5, col = (q & 31) * 4;
        float4 v = xb[q];
        float4 g = *(const float4*)(lg + r * 128 + col);
        float4 be = *(const float4*)(lb + r * 128 + col);
        v.x = (v.x - mu) * rs * g.x + be.x; v.y = (v.y - mu) * rs * g.y + be.y;
        v.z = (v.z - mu) * rs * g.z + be.z; v.w = (v.w - mu) * rs * g.w + be.w;
        __half hx, lx, hy, ly, hz, lz, hw, lw;
        hsplit(v.x, hx, lx); hsplit(v.y, hy, ly); hsplit(v.z, hz, lz); hsplit(v.w, hw, lw);
        uint32_t off = (uint32_t)(r * 136 + col) * 2;
        uint2 uh; uh.x = pack2h(hx, hy); uh.y = pack2h(hz, hw);
        uint2 ul; ul.x = pack2h(lx, ly); ul.y = pack2h(lz, lw);
        *(uint2*)(pAh + off) = uh; *(uint2*)(pAl + off) = ul;
    }

    float acc[16][4];
    zacc<16>(acc);
#pragma unroll
    for (int c = 0; c < 2; c++) {
        load_b<128, 64, 72>(pBh, pBl, g_B0ah, g_B0al, 128, c * 64, tid);
        __syncthreads();
        mma_chunk<4, 2, 4, 2, 136, 72, true>(uAh, uAl, uBh, uBl, aoff, boff, wcp, c * 4, acc);
        __syncthreads();
    }
    epi<2, 4, 2, true>(acc, s_b1, r0, wcp, lane,
        [&](int r, int c, float v) { store_h(pAh, pAl, r * 136 + c, v); });

    zacc<16>(acc);
#pragma unroll
    for (int c = 0; c < 2; c++) {
        load_b<128, 64, 72>(pBh, pBl, g_B0bh, g_B0bl, 128, c * 64, tid);
        __syncthreads();
        mma_chunk<4, 2, 4, 2, 136, 72, true>(uAh, uAl, uBh, uBl, aoff, boff, wcp, c * 4, acc);
        __syncthreads();
    }
    float* ob = out + (long long)b * 28672;
    epi<2, 4, 2, false>(acc, s_b2, r0, wcp, lane,
        [&](int r, int c, float v) { ob[c * 128 + r] = v; });
}

// ---------------- K1: conv1 + TriU(W1a) + hsw + TriU(W1b) -> out[b,128+s,co] -
__global__ __launch_bounds__(256, 2)
void k1_kernel(const float* __restrict__ x, const float* __restrict__ c1b,
               const float* __restrict__ b1a, const float* __restrict__ b1b,
               float* __restrict__ out) {
    extern __shared__ char dsm[];
    __shared__ float s_cb[128], s_ba[64], s_bb[64];
    const int tid = threadIdx.x, lane = tid & 31, wid = tid >> 5;
    const int b = blockIdx.x;
    const int r0c = (wid & 1) * 32, wcpc = wid >> 1;
    const int r0t = (wid & 3) * 32, wcpt = wid >> 2;
    char* pCh = dsm;          char* pCl = dsm + 33792;
    char* pA2h = dsm;         char* pA2l = dsm + 18432;
    char* pA3h = dsm + 36864; char* pA3l = dsm + 55296;
    char* pBh = dsm + 73728;  char* pBl = dsm + 92160;
    const uint32_t u0 = smem_u32(dsm);
    const uint32_t uCh = u0, uCl = u0 + 33792;
    const uint32_t uA2h = u0, uA2l = u0 + 18432;
    const uint32_t uA3h = u0 + 36864, uA3l = u0 + 55296;
    const uint32_t uBh = u0 + 73728, uBl = u0 + 92160;
    const uint32_t aoffc = ((r0c + ((lane >> 3) & 1) * 8 + (lane & 7)) * 264 + (lane >> 4) * 8) * 2;
    const uint32_t aofft = ((r0t + ((lane >> 3) & 1) * 8 + (lane & 7)) * 72 + (lane >> 4) * 8) * 2;
    const uint32_t boff = (((lane >> 4) * 8 + (lane & 7)) * 72 + ((lane >> 3) & 1) * 8) * 2;
    if (tid < 128) s_cb[tid] = c1b[tid];
    if (tid < 64) { s_ba[tid] = b1a[tid]; s_bb[tid] = b1b[tid]; }

    const float4* xb = (const float4*)(x + (long long)b * 16384);
#pragma unroll
    for (int qq = 0; qq < 16; qq++) {
        int q = qq * 256 + tid;
        int r = q >> 6, col = (q & 63) * 4;
        float4 v = xb[q];
        __half hx, lx, hy, ly, hz, lz, hw, lw;
        hsplit(v.x, hx, lx); hsplit(v.y, hy, ly); hsplit(v.z, hz, lz); hsplit(v.w, hw, lw);
        uint32_t off = (uint32_t)(r * 264 + col) * 2;
        uint2 uh; uh.x = pack2h(hx, hy); uh.y = pack2h(hz, hw);
        uint2 ul; ul.x = pack2h(lx, ly); ul.y = pack2h(lz, lw);
        *(uint2*)(pCh + off) = uh; *(uint2*)(pCl + off) = ul;
    }

    float acc[8][4];
    zacc<8>(acc);
#pragma unroll
    for (int c = 0; c < 4; c++) {
        load_b<128, 64, 72>(pBh, pBl, g_Bc1h, g_Bc1l, 256, c * 64, tid);
        __syncthreads();
        mma_chunk<4, 2, 2, 4, 264, 72, false>(uCh, uCl, uBh, uBl, aoffc, boff, wcpc,
                                              c * 4, acc);   // FIX: ks0 = c*4
        __syncthreads();
    }
    epi<2, 2, 4, false>(acc, s_cb, r0c, wcpc, lane,
        [&](int r, int c, float v) { store_h(pA2h, pA2l, c * 72 + r, v); });

    zacc<8>(acc);
    load_b<64, 64, 72>(pBh, pBl, g_B1ah, g_B1al, 64, 0, tid);
    __syncthreads();
    mma_chunk<4, 2, 2, 2, 72, 72, true>(uA2h, uA2l, uBh, uBl, aofft, boff, wcpt, 0, acc);
    __syncthreads();
    epi<2, 2, 2, true>(acc, s_ba, r0t, wcpt, lane,
        [&](int r, int c, float v) { store_h(pA3h, pA3l, r * 72 + c, v); });

    zacc<8>(acc);
    load_b<64, 64, 72>(pBh, pBl, g_B1bh, g_B1bl, 64, 0, tid);
    __syncthreads();
    mma_chunk<4, 2, 2, 2, 72, 72, true>(uA3h, uA3l, uBh, uBl, aofft, boff, wcpt, 0, acc);
    float* ob = out + (long long)b * 28672 + 16384;
    epi<2, 2, 2, false>(acc, s_bb, r0t, wcpt, lane,
        [&](int r, int c, float v) { ob[c * 128 + r] = v; });
}

// ---------------- K2: conv2 + TriU(W2a) + hsw + TriU(W2b), 2 batches/CTA ----
__global__ __launch_bounds__(256, 1)
void k2_kernel(const float* __restrict__ x, const float* __restrict__ c2b,
               const float* __restrict__ b2a, const float* __restrict__ b2b,
               float* __restrict__ out) {
    extern __shared__ char dsm[];
    __shared__ float s_cb[128], s_ba[32], s_bb[32];
    const int tid = threadIdx.x, lane = tid & 31, wid = tid >> 5;
    const int b0 = blockIdx.x * 2;
    const int r0c = (wid & 1) * 32, wcpc = wid >> 1;
    const int r0t = wid * 32;
    char* pCh = dsm;           char* pCl = dsm + 66560;
    char* pA2h = dsm;          char* pA2l = dsm + 20480;
    char* pA3h = dsm + 40960;  char* pA3l = dsm + 61440;
    char* pBh = dsm + 133120;  char* pBl = dsm + 151552;
    const uint32_t u0 = smem_u32(dsm);
    const uint32_t uCh = u0, uCl = u0 + 66560;
    const uint32_t uA2h = u0, uA2l = u0 + 20480;
    const uint32_t uA3h = u0 + 40960, uA3l = u0 + 61440;
    const uint32_t uBh = u0 + 133120, uBl = u0 + 151552;
    const uint32_t aoffc = ((r0c + ((lane >> 3) & 1) * 8 + (lane & 7)) * 520 + (lane >> 4) * 8) * 2;
    const uint32_t aofft = ((r0t + ((lane >> 3) & 1) * 8 + (lane & 7)) * 40 + (lane >> 4) * 8) * 2;
    const uint32_t boffc = (((lane >> 4) * 8 + (lane & 7)) * 72 + ((lane >> 3) & 1) * 8) * 2;
    const uint32_t bofft = (((lane >> 4) * 8 + (lane & 7)) * 40 + ((lane >> 3) & 1) * 8) * 2;
    if (tid < 128) s_cb[tid] = c2b[tid];
    if (tid < 32) { s_ba[tid] = b2a[tid]; s_bb[tid] = b2b[tid]; }

    // rows: (bh, s): 512 contiguous floats at x[(b0+bh)*16384 + s*512]
#pragma unroll
    for (int qq = 0; qq < 32; qq++) {
        int q = qq * 256 + tid;
        int r = q >> 7, col = (q & 127) * 4;
        float4 v = *(const float4*)(x + (long long)(b0 + (r >> 5)) * 16384
                                      + (r & 31) * 512 + col);
        __half hx, lx, hy, ly, hz, lz, hw, lw;
        hsplit(v.x, hx, lx); hsplit(v.y, hy, ly); hsplit(v.z, hz, lz); hsplit(v.w, hw, lw);
        uint32_t off = (uint32_t)(r * 520 + col) * 2;
        uint2 uh; uh.x = pack2h(hx, hy); uh.y = pack2h(hz, hw);
        uint2 ul; ul.x = pack2h(lx, ly); ul.y = pack2h(lz, lw);
        *(uint2*)(pCh + off) = uh; *(uint2*)(pCl + off) = ul;
    }

    float acc[8][4];
    zacc<8>(acc);
#pragma unroll
    for (int c = 0; c < 8; c++) {
        load_b<128, 64, 72>(pBh, pBl, g_Bc2h, g_Bc2l, 512, c * 64, tid);
        __syncthreads();
        mma_chunk<4, 2, 2, 4, 520, 72, false>(uCh, uCl, uBh, uBl, aoffc, boffc, wcpc,
                                              c * 4, acc);   // FIX: ks0 = c*4
        __syncthreads();
    }
    // A2 row = bh*128 + co, col = s (stride 40)
    epi<2, 2, 4, false>(acc, s_cb, r0c, wcpc, lane,
        [&](int r, int c, float v) {
            store_h(pA2h, pA2l, ((r >> 5) * 128 + c) * 40 + (r & 31), v); });

    zacc<8>(acc);
    load_b<32, 32, 40>(pBh, pBl, g_B2ah, g_B2al, 32, 0, tid);
    __syncthreads();
    mma_chunk<2, 2, 2, 1, 40, 40, true>(uA2h, uA2l, uBh, uBl, aofft, bofft, 0, 0, acc);
    __syncthreads();
    epi<2, 2, 1, true>(acc, s_ba, r0t, 0, lane,
        [&](int r, int c, float v) { store_h(pA3h, pA3l, r * 40 + c, v); });

    zacc<8>(acc);
    load_b<32, 32, 40>(pBh, pBl, g_B2bh, g_B2bl, 32, 0, tid);
    __syncthreads();
    mma_chunk<2, 2, 2, 1, 40, 40, true>(uA3h, uA3l, uBh, uBl, aofft, bofft, 0, 0, acc);
    epi<2, 2, 1, false>(acc, s_bb, r0t, 0, lane,
        [&](int r, int c, float v) {
            out[(long long)(b0 + (r >> 7)) * 28672 + 24576 + c * 128 + (r & 127)] = v; });
}

// ---------------------------------------------------------------------------
extern "C" void kernel_launch(void* const* d_in, const int* in_sizes, int n_in,
                              void* d_out, int out_size) {
    const float* x   = (const float*)d_in[0];
    const float* lg  = (const float*)d_in[1];
    const float* lb  = (const float*)d_in[2];
    const float* W0a = (const float*)d_in[3];
    const float* b0a = (const float*)d_in[4];
    const float* W0b = (const float*)d_in[5];
    const float* b0b = (const float*)d_in[6];
    const float* c1w = (const float*)d_in[7];
    const float* c1b = (const float*)d_in[8];
    const float* W1a = (const float*)d_in[9];
    const float* b1a = (const float*)d_in[10];
    const float* W1b = (const float*)d_in[11];
    const float* b1b = (const float*)d_in[12];
    const float* c2w = (const float*)d_in[13];
    const float* c2b = (const float*)d_in[14];
    const float* W2a = (const float*)d_in[15];
    const float* b2a = (const float*)d_in[16];
    const float* W2b = (const float*)d_in[17];
    const float* b2b = (const float*)d_in[18];
    float* out = (float*)d_out;

    const int ds0 = 106496, ds1 = 110592, ds2 = 169984;
    cudaFuncSetAttribute(k0_kernel, cudaFuncAttributeMaxDynamicSharedMemorySize, ds0);
    cudaFuncSetAttribute(k1_kernel, cudaFuncAttributeMaxDynamicSharedMemorySize, ds1);
    cudaFuncSetAttribute(k2_kernel, cudaFuncAttributeMaxDynamicSharedMemorySize, ds2);

    prep_k<<<128, 256>>>(W0a, W0b, W1a, W1b, W2a, W2b, c1w, c2w);
    k0_kernel<<<2048, 256, ds0>>>(x, lg, lb, b0a, b0b, out);
    k1_kernel<<<2048, 256, ds1>>>(x, c1b, b1a, b1b, out);
    k2_kernel<<<1024, 256, ds2>>>(x, c2b, b2a, b2b, out);
}

// round 10
// speedup vs baseline: 1.3392x; 1.0495x over previous
#include <cuda_runtime.h>
#include <cuda_fp16.h>
#include <cstdint>

// MultiScaleTimeMixer, fused per scale. HMMA fp16 hi/lo 3-pass, fp32 acc.

__device__ __align__(16) __half g_B0ah[16384], g_B0al[16384];
__device__ __align__(16) __half g_B0bh[16384], g_B0bl[16384];
__device__ __align__(16) __half g_B1ah[4096],  g_B1al[4096];
__device__ __align__(16) __half g_B1bh[4096],  g_B1bl[4096];
__device__ __align__(16) __half g_B2ah[1024],  g_B2al[1024];
__device__ __align__(16) __half g_B2bh[1024],  g_B2bl[1024];
__device__ __align__(16) __half g_Bc1h[128*256], g_Bc1l[128*256];
__device__ __align__(16) __half g_Bc2h[128*512], g_Bc2l[128*512];

__device__ __forceinline__ uint32_t smem_u32(const void* p) {
    uint32_t a;
    asm("{ .reg .u64 t; cvta.to.shared.u64 t, %1; cvt.u32.u64 %0, t; }" : "=r"(a) : "l"(p));
    return a;
}
#define LDSM4(r, addr)                                                           \
    asm volatile("ldmatrix.sync.aligned.m8n8.x4.shared.b16 {%0,%1,%2,%3}, [%4];" \
        : "=r"((r)[0]), "=r"((r)[1]), "=r"((r)[2]), "=r"((r)[3]) : "r"(addr))
#define MMA16816(d, a, b0, b1)                                                   \
    asm volatile("mma.sync.aligned.m16n8k16.row.col.f32.f16.f16.f32 "            \
        "{%0,%1,%2,%3}, {%4,%5,%6,%7}, {%8,%9}, {%0,%1,%2,%3};"                  \
        : "+f"((d)[0]), "+f"((d)[1]), "+f"((d)[2]), "+f"((d)[3])                  \
        : "r"((a)[0]), "r"((a)[1]), "r"((a)[2]), "r"((a)[3]), "r"(b0), "r"(b1))

__device__ __forceinline__ uint32_t pack2h(__half a, __half b) {
    return (uint32_t)__half_as_ushort(a) | ((uint32_t)__half_as_ushort(b) << 16);
}
__device__ __forceinline__ void hsplit(float v, __half& h, __half& l) {
    h = __float2half_rn(v); l = __float2half_rn(v - __half2float(h));
}
__device__ __forceinline__ float hswish(float v) {
    return v * fminf(fmaxf(v + 3.f, 0.f), 6.f) * (1.f / 6.f);
}
__device__ __forceinline__ void store_h(char* pH, char* pL, int idx, float v) {
    __half h, l; hsplit(v, h, l);
    *(__half*)(pH + idx * 2) = h; *(__half*)(pL + idx * 2) = l;
}

__global__ void prep_k(const float* __restrict__ W0a, const float* __restrict__ W0b,
                       const float* __restrict__ W1a, const float* __restrict__ W1b,
                       const float* __restrict__ W2a, const float* __restrict__ W2b,
                       const float* __restrict__ c1w, const float* __restrict__ c2w) {
    int tid = blockIdx.x * blockDim.x + threadIdx.x, st = gridDim.x * blockDim.x;
    for (int i = tid; i < 16384; i += st) {
        int n = i >> 7, k = i & 127; float m = (k <= n) ? 1.f : 0.f;
        hsplit(m * W0a[i], g_B0ah[i], g_B0al[i]);
        hsplit(m * W0b[i], g_B0bh[i], g_B0bl[i]);
    }
    for (int i = tid; i < 4096; i += st) {
        int n = i >> 6, k = i & 63; float m = (k <= n) ? 1.f : 0.f;
        hsplit(m * W1a[i], g_B1ah[i], g_B1al[i]);
        hsplit(m * W1b[i], g_B1bh[i], g_B1bl[i]);
    }
    for (int i = tid; i < 1024; i += st) {
        int n = i >> 5, k = i & 31; float m = (k <= n) ? 1.f : 0.f;
        hsplit(m * W2a[i], g_B2ah[i], g_B2al[i]);
        hsplit(m * W2b[i], g_B2bh[i], g_B2bl[i]);
    }
    for (int i = tid; i < 128 * 256; i += st) {
        int co = i >> 8, k = i & 255;
        hsplit(c1w[co * 256 + (k & 127) * 2 + (k >> 7)], g_Bc1h[i], g_Bc1l[i]);
    }
    for (int i = tid; i < 128 * 512; i += st) {
        int co = i >> 9, k = i & 511;
        hsplit(c2w[co * 512 + (k & 127) * 4 + (k >> 7)], g_Bc2h[i], g_Bc2l[i]);
    }
}

template<int NROWS, int KCH, int SBH>
__device__ __forceinline__ void load_b(char* pBh, char* pBl,
    const __half* __restrict__ gh, const __half* __restrict__ gl,
    int ktot, int kbase, int tid) {
    constexpr int PER = KCH / 8, TOT = NROWS * PER;
    for (int i = tid; i < TOT; i += 256) {
        int n = i / PER, kq = i % PER;
        uint32_t off = (uint32_t)(n * SBH + kq * 8) * 2;
        *(uint4*)(pBh + off) = *(const uint4*)(gh + n * ktot + kbase + kq * 8);
        *(uint4*)(pBl + off) = *(const uint4*)(gl + n * ktot + kbase + kq * 8);
    }
}

// 3-pass MMA over KS k16-steps. A indexed by ksg = ks0+kk (ks0=0 when A is
// chunk-local); B holds ONLY the current chunk (stride SBH, indexed by kk).
// Warp covers RB 16-row blocks x NG col groups gg=g*WC+wcp. TRI: skip ksg>gg.
template<int KS, int RB, int NG, int WC, int SAH, int SBH, bool TRI>
__device__ __forceinline__ void mma_chunk(uint32_t uAh, uint32_t uAl,
    uint32_t uBh, uint32_t uBl, uint32_t aoff, uint32_t boff,
    int wcp, int ks0, float (*acc)[4]) {
#pragma unroll
    for (int kk = 0; kk < KS; kk++) {
        int ksg = ks0 + kk;
        uint32_t ah[RB][4], al[RB][4];
        if (!TRI || ksg <= (NG - 1) * WC + wcp) {
#pragma unroll
            for (int rb = 0; rb < RB; rb++) {
                LDSM4(ah[rb], uAh + aoff + rb * (16 * SAH * 2) + (uint32_t)ksg * 32);
                LDSM4(al[rb], uAl + aoff + rb * (16 * SAH * 2) + (uint32_t)ksg * 32);
            }
        }
#pragma unroll
        for (int g = 0; g < NG; g++) {
            int gg = g * WC + wcp;
            if (TRI && ksg > gg) continue;
            uint32_t bh[4], bl[4];
            LDSM4(bh, uBh + boff + (uint32_t)(gg * (16 * SBH * 2) + kk * 32));
            LDSM4(bl, uBl + boff + (uint32_t)(gg * (16 * SBH * 2) + kk * 32));
#pragma unroll
            for (int rb = 0; rb < RB; rb++) {
                float* a0 = acc[(rb * NG + g) * 2]; float* a1 = acc[(rb * NG + g) * 2 + 1];
                MMA16816(a0, ah[rb], bh[0], bh[1]); MMA16816(a1, ah[rb], bh[2], bh[3]);
                MMA16816(a0, al[rb], bh[0], bh[1]); MMA16816(a1, al[rb], bh[2], bh[3]);
                MMA16816(a0, ah[rb], bl[0], bl[1]); MMA16816(a1, ah[rb], bl[2], bl[3]);
            }
        }
    }
}

template<int NA> __device__ __forceinline__ void zacc(float (*acc)[4]) {
#pragma unroll
    for (int i = 0; i < NA; i++) { acc[i][0] = acc[i][1] = acc[i][2] = acc[i][3] = 0.f; }
}

template<int RB, int NG, int WC, bool HSW, class F>
__device__ __forceinline__ void epi(float (*acc)[4], const float* sb,
                                    int r0, int wcp, int lane, F f) {
#pragma unroll
    for (int rb = 0; rb < RB; rb++)
#pragma unroll
    for (int g = 0; g < NG; g++)
#pragma unroll
    for (int j = 0; j < 2; j++) {
        const float* a = acc[(rb * NG + g) * 2 + j];
        int cc = (g * WC + wcp) * 16 + j * 8 + 2 * (lane & 3);
        int r = r0 + rb * 16 + (lane >> 2);
        float b0 = sb[cc], b1 = sb[cc + 1];
        float v0 = a[0] + b0, v1 = a[1] + b1, v2 = a[2] + b0, v3 = a[3] + b1;
        if (HSW) { v0 = hswish(v0); v1 = hswish(v1); v2 = hswish(v2); v3 = hswish(v3); }
        f(r, cc, v0); f(r, cc + 1, v1); f(r + 8, cc, v2); f(r + 8, cc + 1, v3);
    }
}

// ---------------- K0: LN + TriU(W0a) + hsw + TriU(W0b) -> out[b,j,t] --------
__global__ __launch_bounds__(256, 2)
void k0_kernel(const float* __restrict__ x, const float* __restrict__ lg,
               const float* __restrict__ lb, const float* __restrict__ b0a,
               const float* __restrict__ b0b, float* __restrict__ out) {
    extern __shared__ char dsm[];
    __shared__ float s_s[8], s_q[8], s_ms[2], s_b1[128], s_b2[128];
    const int tid = threadIdx.x, lane = tid & 31, wid = tid >> 5;
    const int wcp = wid >> 2, r0 = (wid & 3) * 32, b = blockIdx.x;
    char* pAh = dsm; char* pAl = dsm + 34816;
    char* pBh = dsm + 69632; char* pBl = dsm + 88064;
    const uint32_t uA = smem_u32(dsm);
    const uint32_t uAh = uA, uAl = uA + 34816, uBh = uA + 69632, uBl = uA + 88064;
    const uint32_t aoff = ((r0 + ((lane >> 3) & 1) * 8 + (lane & 7)) * 136 + (lane >> 4) * 8) * 2;
    const uint32_t boff = (((lane >> 4) * 8 + (lane & 7)) * 72 + ((lane >> 3) & 1) * 8) * 2;
    if (tid < 128) { s_b1[tid] = b0a[tid]; s_b2[tid] = b0b[tid]; }

    const float4* xb = (const float4*)(x + (long long)b * 16384);
    float sm = 0.f, sq = 0.f;
#pragma unroll
    for (int q = 0; q < 16; q++) {
        float4 v = xb[q * 256 + tid];
        sm += v.x + v.y + v.z + v.w;
        sq += v.x * v.x + v.y * v.y + v.z * v.z + v.w * v.w;
    }
#pragma unroll
    for (int o = 16; o > 0; o >>= 1) {
        sm += __shfl_down_sync(~0u, sm, o); sq += __shfl_down_sync(~0u, sq, o);
    }
    if (lane == 0) { s_s[wid] = sm; s_q[wid] = sq; }
    __syncthreads();
    if (tid == 0) {
        float S = 0.f, Q = 0.f;
#pragma unroll
        for (int i = 0; i < 8; i++) { S += s_s[i]; Q += s_q[i]; }
        float mu = S * (1.f / 16384.f);
        s_ms[0] = mu; s_ms[1] = rsqrtf(Q * (1.f / 16384.f) - mu * mu + 1e-5f);
    }
    __syncthreads();
    const float mu = s_ms[0], rs = s_ms[1];
#pragma unroll
    for (int qq = 0; qq < 16; qq++) {
        int q = qq * 256 + tid;
        int r = q >> 5, col = (q & 31) * 4;
        float4 v = xb[q];
        float4 g = *(const float4*)(lg + r * 128 + col);
        float4 be = *(const float4*)(lb + r * 128 + col);
        v.x = (v.x - mu) * rs * g.x + be.x; v.y = (v.y - mu) * rs * g.y + be.y;
        v.z = (v.z - mu) * rs * g.z + be.z; v.w = (v.w - mu) * rs * g.w + be.w;
        __half hx, lx, hy, ly, hz, lz, hw, lw;
        hsplit(v.x, hx, lx); hsplit(v.y, hy, ly); hsplit(v.z, hz, lz); hsplit(v.w, hw, lw);
        uint32_t off = (uint32_t)(r * 136 + col) * 2;
        uint2 uh; uh.x = pack2h(hx, hy); uh.y = pack2h(hz, hw);
        uint2 ul; ul.x = pack2h(lx, ly); ul.y = pack2h(lz, lw);
        *(uint2*)(pAh + off) = uh; *(uint2*)(pAl + off) = ul;
    }

    float acc[16][4];
    zacc<16>(acc);
#pragma unroll
    for (int c = 0; c < 2; c++) {
        load_b<128, 64, 72>(pBh, pBl, g_B0ah, g_B0al, 128, c * 64, tid);
        __syncthreads();
        mma_chunk<4, 2, 4, 2, 136, 72, true>(uAh, uAl, uBh, uBl, aoff, boff, wcp, c * 4, acc);
        __syncthreads();
    }
    epi<2, 4, 2, true>(acc, s_b1, r0, wcp, lane,
        [&](int r, int c, float v) { store_h(pAh, pAl, r * 136 + c, v); });

    zacc<16>(acc);
#pragma unroll
    for (int c = 0; c < 2; c++) {
        load_b<128, 64, 72>(pBh, pBl, g_B0bh, g_B0bl, 128, c * 64, tid);
        __syncthreads();
        mma_chunk<4, 2, 4, 2, 136, 72, true>(uAh, uAl, uBh, uBl, aoff, boff, wcp, c * 4, acc);
        __syncthreads();
    }
    float* ob = out + (long long)b * 28672;
    epi<2, 4, 2, false>(acc, s_b2, r0, wcp, lane,
        [&](int r, int c, float v) { ob[c * 128 + r] = v; });
}

// ---------------- K1: conv1 + TriU(W1a) + hsw + TriU(W1b) -> out[b,128+s,co] -
__global__ __launch_bounds__(256, 2)
void k1_kernel(const float* __restrict__ x, const float* __restrict__ c1b,
               const float* __restrict__ b1a, const float* __restrict__ b1b,
               float* __restrict__ out) {
    extern __shared__ char dsm[];
    __shared__ float s_cb[128], s_ba[64], s_bb[64];
    const int tid = threadIdx.x, lane = tid & 31, wid = tid >> 5;
    const int b = blockIdx.x;
    const int r0c = (wid & 1) * 32, wcpc = wid >> 1;
    const int r0t = (wid & 3) * 32, wcpt = wid >> 2;
    char* pCh = dsm;          char* pCl = dsm + 33792;
    char* pA2h = dsm;         char* pA2l = dsm + 18432;
    char* pA3h = dsm + 36864; char* pA3l = dsm + 55296;
    char* pBh = dsm + 73728;  char* pBl = dsm + 92160;
    const uint32_t u0 = smem_u32(dsm);
    const uint32_t uCh = u0, uCl = u0 + 33792;
    const uint32_t uA2h = u0, uA2l = u0 + 18432;
    const uint32_t uA3h = u0 + 36864, uA3l = u0 + 55296;
    const uint32_t uBh = u0 + 73728, uBl = u0 + 92160;
    const uint32_t aoffc = ((r0c + ((lane >> 3) & 1) * 8 + (lane & 7)) * 264 + (lane >> 4) * 8) * 2;
    const uint32_t aofft = ((r0t + ((lane >> 3) & 1) * 8 + (lane & 7)) * 72 + (lane >> 4) * 8) * 2;
    const uint32_t boff = (((lane >> 4) * 8 + (lane & 7)) * 72 + ((lane >> 3) & 1) * 8) * 2;
    if (tid < 128) s_cb[tid] = c1b[tid];
    if (tid < 64) { s_ba[tid] = b1a[tid]; s_bb[tid] = b1b[tid]; }

    const float4* xb = (const float4*)(x + (long long)b * 16384);
#pragma unroll
    for (int qq = 0; qq < 16; qq++) {
        int q = qq * 256 + tid;
        int r = q >> 6, col = (q & 63) * 4;
        float4 v = xb[q];
        __half hx, lx, hy, ly, hz, lz, hw, lw;
        hsplit(v.x, hx, lx); hsplit(v.y, hy, ly); hsplit(v.z, hz, lz); hsplit(v.w, hw, lw);
        uint32_t off = (uint32_t)(r * 264 + col) * 2;
        uint2 uh; uh.x = pack2h(hx, hy); uh.y = pack2h(hz, hw);
        uint2 ul; ul.x = pack2h(lx, ly); ul.y = pack2h(lz, lw);
        *(uint2*)(pCh + off) = uh; *(uint2*)(pCl + off) = ul;
    }

    float acc[8][4];
    zacc<8>(acc);
#pragma unroll
    for (int c = 0; c < 4; c++) {
        load_b<128, 64, 72>(pBh, pBl, g_Bc1h, g_Bc1l, 256, c * 64, tid);
        __syncthreads();
        mma_chunk<4, 2, 2, 4, 264, 72, false>(uCh, uCl, uBh, uBl, aoffc, boff, wcpc,
                                              c * 4, acc);   // A resident: ks0 = c*4
        __syncthreads();
    }
    epi<2, 2, 4, false>(acc, s_cb, r0c, wcpc, lane,
        [&](int r, int c, float v) { store_h(pA2h, pA2l, c * 72 + r, v); });

    zacc<8>(acc);
    load_b<64, 64, 72>(pBh, pBl, g_B1ah, g_B1al, 64, 0, tid);
    __syncthreads();
    mma_chunk<4, 2, 2, 2, 72, 72, true>(uA2h, uA2l, uBh, uBl, aofft, boff, wcpt, 0, acc);
    __syncthreads();
    epi<2, 2, 2, true>(acc, s_ba, r0t, wcpt, lane,
        [&](int r, int c, float v) { store_h(pA3h, pA3l, r * 72 + c, v); });

    zacc<8>(acc);
    load_b<64, 64, 72>(pBh, pBl, g_B1bh, g_B1bl, 64, 0, tid);
    __syncthreads();
    mma_chunk<4, 2, 2, 2, 72, 72, true>(uA3h, uA3l, uBh, uBl, aofft, boff, wcpt, 0, acc);
    float* ob = out + (long long)b * 28672 + 16384;
    epi<2, 2, 2, false>(acc, s_bb, r0t, wcpt, lane,
        [&](int r, int c, float v) { ob[c * 128 + r] = v; });
}

// ---------------- K2: conv2 + TriU(W2a) + hsw + TriU(W2b), 2 batches/CTA ----
// smem layout (96256 B total, 2 CTAs/SM):
//   [0,40960)      A2 (hi 0, lo 20480)           rows (bh*128+co) x s, stride 40
//   [40960,59392)  conv A chunk (hi 40960, lo 50176)  64 rows x 64k, stride 72
//   [59392,96256)  conv B chunk (hi 59392, lo 77824)  128 co x 64k, stride 72
//   [40960,81920)  A3 (hi 40960, lo 61440)       aliases dead conv bufs
//   [81920,87040)  tri B (hi 81920, lo 84480)    32 x 32k, stride 40
__global__ __launch_bounds__(256, 2)
void k2_kernel(const float* __restrict__ x, const float* __restrict__ c2b,
               const float* __restrict__ b2a, const float* __restrict__ b2b,
               float* __restrict__ out) {
    extern __shared__ char dsm[];
    __shared__ float s_cb[128], s_ba[32], s_bb[32];
    const int tid = threadIdx.x, lane = tid & 31, wid = tid >> 5;
    const int b0 = blockIdx.x * 2;
    const int r0c = (wid & 1) * 32, wcpc = wid >> 1;
    const int r0t = wid * 32;
    char* pA2h = dsm;          char* pA2l = dsm + 20480;
    char* pCAh = dsm + 40960;  char* pCAl = dsm + 50176;
    char* pCBh = dsm + 59392;  char* pCBl = dsm + 77824;
    char* pA3h = dsm + 40960;  char* pA3l = dsm + 61440;
    char* pTBh = dsm + 81920;  char* pTBl = dsm + 84480;
    const uint32_t u0 = smem_u32(dsm);
    const uint32_t uA2h = u0, uA2l = u0 + 20480;
    const uint32_t uCAh = u0 + 40960, uCAl = u0 + 50176;
    const uint32_t uCBh = u0 + 59392, uCBl = u0 + 77824;
    const uint32_t uA3h = u0 + 40960, uA3l = u0 + 61440;
    const uint32_t uTBh = u0 + 81920, uTBl = u0 + 84480;
    const uint32_t aoffc = ((r0c + ((lane >> 3) & 1) * 8 + (lane & 7)) * 72 + (lane >> 4) * 8) * 2;
    const uint32_t aofft = ((r0t + ((lane >> 3) & 1) * 8 + (lane & 7)) * 40 + (lane >> 4) * 8) * 2;
    const uint32_t boffc = (((lane >> 4) * 8 + (lane & 7)) * 72 + ((lane >> 3) & 1) * 8) * 2;
    const uint32_t bofft = (((lane >> 4) * 8 + (lane & 7)) * 40 + ((lane >> 3) & 1) * 8) * 2;
    if (tid < 128) s_cb[tid] = c2b[tid];
    if (tid < 32) { s_ba[tid] = b2a[tid]; s_bb[tid] = b2b[tid]; }

    float acc[8][4];
    zacc<8>(acc);
    // conv: M=64 rows (bh,s), K=512 in 8 chunks of 64; A staged per chunk
#pragma unroll 1
    for (int c = 0; c < 8; c++) {
        // stage A chunk: row r=(bh*32+s), cols 64 from x[(b0+bh)*16384 + s*512 + c*64 ..]
#pragma unroll
        for (int qq = 0; qq < 4; qq++) {
            int q = qq * 256 + tid;
            int r = q >> 4, col4 = (q & 15) * 4;
            float4 v = *(const float4*)(x + (long long)(b0 + (r >> 5)) * 16384
                                          + (r & 31) * 512 + c * 64 + col4);
            __half hx, lx, hy, ly, hz, lz, hw, lw;
            hsplit(v.x, hx, lx); hsplit(v.y, hy, ly); hsplit(v.z, hz, lz); hsplit(v.w, hw, lw);
            uint32_t off = (uint32_t)(r * 72 + col4) * 2;
            uint2 uh; uh.x = pack2h(hx, hy); uh.y = pack2h(hz, hw);
            uint2 ul; ul.x = pack2h(lx, ly); ul.y = pack2h(lz, lw);
            *(uint2*)(pCAh + off) = uh; *(uint2*)(pCAl + off) = ul;
        }
        load_b<128, 64, 72>(pCBh, pCBl, g_Bc2h, g_Bc2l, 512, c * 64, tid);
        __syncthreads();
        // A chunk-local => ks0 = 0 (both A and B indexed by kk)
        mma_chunk<4, 2, 2, 4, 72, 72, false>(uCAh, uCAl, uCBh, uCBl, aoffc, boffc,
                                             wcpc, 0, acc);
        __syncthreads();
    }
    // conv + bias -> A2, row = bh*128 + co, col = s (stride 40)
    epi<2, 2, 4, false>(acc, s_cb, r0c, wcpc, lane,
        [&](int r, int c, float v) {
            store_h(pA2h, pA2l, ((r >> 5) * 128 + c) * 40 + (r & 31), v); });

    zacc<8>(acc);
    load_b<32, 32, 40>(pTBh, pTBl, g_B2ah, g_B2al, 32, 0, tid);
    __syncthreads();
    mma_chunk<2, 2, 2, 1, 40, 40, true>(uA2h, uA2l, uTBh, uTBl, aofft, bofft, 0, 0, acc);
    __syncthreads();
    epi<2, 2, 1, true>(acc, s_ba, r0t, 0, lane,
        [&](int r, int c, float v) { store_h(pA3h, pA3l, r * 40 + c, v); });

    zacc<8>(acc);
    load_b<32, 32, 40>(pTBh, pTBl, g_B2bh, g_B2bl, 32, 0, tid);
    __syncthreads();
    mma_chunk<2, 2, 2, 1, 40, 40, true>(uA3h, uA3l, uTBh, uTBl, aofft, bofft, 0, 0, acc);
    epi<2, 2, 1, false>(acc, s_bb, r0t, 0, lane,
        [&](int r, int c, float v) {
            out[(long long)(b0 + (r >> 7)) * 28672 + 24576 + c * 128 + (r & 127)] = v; });
}

// ---------------------------------------------------------------------------
extern "C" void kernel_launch(void* const* d_in, const int* in_sizes, int n_in,
                              void* d_out, int out_size) {
    const float* x   = (const float*)d_in[0];
    const float* lg  = (const float*)d_in[1];
    const float* lb  = (const float*)d_in[2];
    const float* W0a = (const float*)d_in[3];
    const float* b0a = (const float*)d_in[4];
    const float* W0b = (const float*)d_in[5];
    const float* b0b = (const float*)d_in[6];
    const float* c1w = (const float*)d_in[7];
    const float* c1b = (const float*)d_in[8];
    const float* W1a = (const float*)d_in[9];
    const float* b1a = (const float*)d_in[10];
    const float* W1b = (const float*)d_in[11];
    const float* b1b = (const float*)d_in[12];
    const float* c2w = (const float*)d_in[13];
    const float* c2b = (const float*)d_in[14];
    const float* W2a = (const float*)d_in[15];
    const float* b2a = (const float*)d_in[16];
    const float* W2b = (const float*)d_in[17];
    const float* b2b = (const float*)d_in[18];
    float* out = (float*)d_out;

    const int ds0 = 106496, ds1 = 110592, ds2 = 96256;
    cudaFuncSetAttribute(k0_kernel, cudaFuncAttributeMaxDynamicSharedMemorySize, ds0);
    cudaFuncSetAttribute(k1_kernel, cudaFuncAttributeMaxDynamicSharedMemorySize, ds1);
    cudaFuncSetAttribute(k2_kernel, cudaFuncAttributeMaxDynamicSharedMemorySize, ds2);

    prep_k<<<128, 256>>>(W0a, W0b, W1a, W1b, W2a, W2b, c1w, c2w);
    k0_kernel<<<2048, 256, ds0>>>(x, lg, lb, b0a, b0b, out);
    k1_kernel<<<2048, 256, ds1>>>(x, c1b, b1a, b1b, out);
    k2_kernel<<<1024, 256, ds2>>>(x, c2b, b2a, b2b, out);
}

// round 11
// speedup vs baseline: 1.3490x; 1.0073x over previous
#include <cuda_runtime.h>
#include <cuda_fp16.h>
#include <cstdint>

// MultiScaleTimeMixer: ONE fused kernel, one batch per CTA, 3 phases.
// HMMA fp16 hi/lo 3-pass, fp32 acc.

__device__ __align__(16) __half g_B0ah[16384], g_B0al[16384];
__device__ __align__(16) __half g_B0bh[16384], g_B0bl[16384];
__device__ __align__(16) __half g_B1ah[4096],  g_B1al[4096];
__device__ __align__(16) __half g_B1bh[4096],  g_B1bl[4096];
__device__ __align__(16) __half g_B2ah[1024],  g_B2al[1024];
__device__ __align__(16) __half g_B2bh[1024],  g_B2bl[1024];
__device__ __align__(16) __half g_Bc1h[128*256], g_Bc1l[128*256];
__device__ __align__(16) __half g_Bc2h[128*512], g_Bc2l[128*512];

__device__ __forceinline__ uint32_t smem_u32(const void* p) {
    uint32_t a;
    asm("{ .reg .u64 t; cvta.to.shared.u64 t, %1; cvt.u32.u64 %0, t; }" : "=r"(a) : "l"(p));
    return a;
}
#define LDSM4(r, addr)                                                           \
    asm volatile("ldmatrix.sync.aligned.m8n8.x4.shared.b16 {%0,%1,%2,%3}, [%4];" \
        : "=r"((r)[0]), "=r"((r)[1]), "=r"((r)[2]), "=r"((r)[3]) : "r"(addr))
#define MMA16816(d, a, b0, b1)                                                   \
    asm volatile("mma.sync.aligned.m16n8k16.row.col.f32.f16.f16.f32 "            \
        "{%0,%1,%2,%3}, {%4,%5,%6,%7}, {%8,%9}, {%0,%1,%2,%3};"                  \
        : "+f"((d)[0]), "+f"((d)[1]), "+f"((d)[2]), "+f"((d)[3])                  \
        : "r"((a)[0]), "r"((a)[1]), "r"((a)[2]), "r"((a)[3]), "r"(b0), "r"(b1))

__device__ __forceinline__ uint32_t pack2h(__half a, __half b) {
    return (uint32_t)__half_as_ushort(a) | ((uint32_t)__half_as_ushort(b) << 16);
}
__device__ __forceinline__ void hsplit(float v, __half& h, __half& l) {
    h = __float2half_rn(v); l = __float2half_rn(v - __half2float(h));
}
__device__ __forceinline__ float hswish(float v) {
    return v * fminf(fmaxf(v + 3.f, 0.f), 6.f) * (1.f / 6.f);
}
__device__ __forceinline__ void store_h(char* pH, char* pL, int idx, float v) {
    __half h, l; hsplit(v, h, l);
    *(__half*)(pH + idx * 2) = h; *(__half*)(pL + idx * 2) = l;
}
// split a float4 and store both planes at byte offset off (stride-agnostic)
__device__ __forceinline__ void split4(char* pH, char* pL, uint32_t off, float4 v) {
    __half hx, lx, hy, ly, hz, lz, hw, lw;
    hsplit(v.x, hx, lx); hsplit(v.y, hy, ly); hsplit(v.z, hz, lz); hsplit(v.w, hw, lw);
    uint2 uh; uh.x = pack2h(hx, hy); uh.y = pack2h(hz, hw);
    uint2 ul; ul.x = pack2h(lx, ly); ul.y = pack2h(lz, lw);
    *(uint2*)(pH + off) = uh; *(uint2*)(pL + off) = ul;
}

__global__ void prep_k(const float* __restrict__ W0a, const float* __restrict__ W0b,
                       const float* __restrict__ W1a, const float* __restrict__ W1b,
                       const float* __restrict__ W2a, const float* __restrict__ W2b,
                       const float* __restrict__ c1w, const float* __restrict__ c2w) {
    int tid = blockIdx.x * blockDim.x + threadIdx.x, st = gridDim.x * blockDim.x;
    for (int i = tid; i < 16384; i += st) {
        int n = i >> 7, k = i & 127; float m = (k <= n) ? 1.f : 0.f;
        hsplit(m * W0a[i], g_B0ah[i], g_B0al[i]);
        hsplit(m * W0b[i], g_B0bh[i], g_B0bl[i]);
    }
    for (int i = tid; i < 4096; i += st) {
        int n = i >> 6, k = i & 63; float m = (k <= n) ? 1.f : 0.f;
        hsplit(m * W1a[i], g_B1ah[i], g_B1al[i]);
        hsplit(m * W1b[i], g_B1bh[i], g_B1bl[i]);
    }
    for (int i = tid; i < 1024; i += st) {
        int n = i >> 5, k = i & 31; float m = (k <= n) ? 1.f : 0.f;
        hsplit(m * W2a[i], g_B2ah[i], g_B2al[i]);
        hsplit(m * W2b[i], g_B2bh[i], g_B2bl[i]);
    }
    for (int i = tid; i < 128 * 256; i += st) {
        int co = i >> 8, k = i & 255;
        hsplit(c1w[co * 256 + (k & 127) * 2 + (k >> 7)], g_Bc1h[i], g_Bc1l[i]);
    }
    for (int i = tid; i < 128 * 512; i += st) {
        int co = i >> 9, k = i & 511;
        hsplit(c2w[co * 512 + (k & 127) * 4 + (k >> 7)], g_Bc2h[i], g_Bc2l[i]);
    }
}

template<int NROWS, int KCH, int SBH>
__device__ __forceinline__ void load_b(char* pBh, char* pBl,
    const __half* __restrict__ gh, const __half* __restrict__ gl,
    int ktot, int kbase, int tid) {
    constexpr int PER = KCH / 8, TOT = NROWS * PER;
    for (int i = tid; i < TOT; i += 256) {
        int n = i / PER, kq = i % PER;
        uint32_t off = (uint32_t)(n * SBH + kq * 8) * 2;
        *(uint4*)(pBh + off) = *(const uint4*)(gh + n * ktot + kbase + kq * 8);
        *(uint4*)(pBl + off) = *(const uint4*)(gl + n * ktot + kbase + kq * 8);
    }
}

// 3-pass MMA over KS k16-steps. A indexed by ksg = ks0+kk (ks0 = chunk*4 when
// A is K-resident, 0 when A is chunk-local); B holds ONLY the current chunk
// (stride SBH, indexed by kk). Warp: RB row-blocks x NG col groups gg=g*WC+wcp.
// TRI: skip blocks with ksg > gg (tril weights).
template<int KS, int RB, int NG, int WC, int SAH, int SBH, bool TRI>
__device__ __forceinline__ void mma_chunk(uint32_t uAh, uint32_t uAl,
    uint32_t uBh, uint32_t uBl, uint32_t aoff, uint32_t boff,
    int wcp, int ks0, float (*acc)[4]) {
#pragma unroll
    for (int kk = 0; kk < KS; kk++) {
        int ksg = ks0 + kk;
        uint32_t ah[RB][4], al[RB][4];
        if (!TRI || ksg <= (NG - 1) * WC + wcp) {
#pragma unroll
            for (int rb = 0; rb < RB; rb++) {
                LDSM4(ah[rb], uAh + aoff + rb * (16 * SAH * 2) + (uint32_t)ksg * 32);
                LDSM4(al[rb], uAl + aoff + rb * (16 * SAH * 2) + (uint32_t)ksg * 32);
            }
        }
#pragma unroll
        for (int g = 0; g < NG; g++) {
            int gg = g * WC + wcp;
            if (TRI && ksg > gg) continue;
            uint32_t bh[4], bl[4];
            LDSM4(bh, uBh + boff + (uint32_t)(gg * (16 * SBH * 2) + kk * 32));
            LDSM4(bl, uBl + boff + (uint32_t)(gg * (16 * SBH * 2) + kk * 32));
#pragma unroll
            for (int rb = 0; rb < RB; rb++) {
                float* a0 = acc[(rb * NG + g) * 2]; float* a1 = acc[(rb * NG + g) * 2 + 1];
                MMA16816(a0, ah[rb], bh[0], bh[1]); MMA16816(a1, ah[rb], bh[2], bh[3]);
                MMA16816(a0, al[rb], bh[0], bh[1]); MMA16816(a1, al[rb], bh[2], bh[3]);
                MMA16816(a0, ah[rb], bl[0], bl[1]); MMA16816(a1, ah[rb], bl[2], bl[3]);
            }
        }
    }
}

template<int NA> __device__ __forceinline__ void zacc(float (*acc)[4]) {
#pragma unroll
    for (int i = 0; i < NA; i++) { acc[i][0] = acc[i][1] = acc[i][2] = acc[i][3] = 0.f; }
}

template<int RB, int NG, int WC, bool HSW, class F>
__device__ __forceinline__ void epi(float (*acc)[4], const float* sb,
                                    int r0, int wcp, int lane, F f) {
#pragma unroll
    for (int rb = 0; rb < RB; rb++)
#pragma unroll
    for (int g = 0; g < NG; g++)
#pragma unroll
    for (int j = 0; j < 2; j++) {
        const float* a = acc[(rb * NG + g) * 2 + j];
        int cc = (g * WC + wcp) * 16 + j * 8 + 2 * (lane & 3);
        int r = r0 + rb * 16 + (lane >> 2);
        float b0 = sb[cc], b1 = sb[cc + 1];
        float v0 = a[0] + b0, v1 = a[1] + b1, v2 = a[2] + b0, v3 = a[3] + b1;
        if (HSW) { v0 = hswish(v0); v1 = hswish(v1); v2 = hswish(v2); v3 = hswish(v3); }
        f(r, cc, v0); f(r, cc + 1, v1); f(r + 8, cc, v2); f(r + 8, cc + 1, v3);
    }
}

// ---------------------------------------------------------------------------
// mega kernel: one CTA = one batch, all three scales.
// dsmem = 110592 B, 2 CTAs/SM.
// ---------------------------------------------------------------------------
__global__ __launch_bounds__(256, 2)
void mega_kernel(const float* __restrict__ x, const float* __restrict__ lg,
                 const float* __restrict__ lb,
                 const float* __restrict__ b0a, const float* __restrict__ b0b,
                 const float* __restrict__ c1b, const float* __restrict__ b1a,
                 const float* __restrict__ b1b,
                 const float* __restrict__ c2b, const float* __restrict__ b2a,
                 const float* __restrict__ b2b,
                 float* __restrict__ out) {
    extern __shared__ char dsm[];
    __shared__ float s_s[8], s_q[8], s_ms[2], s_b1[128], s_b2[128], s_b3[128];
    const int tid = threadIdx.x, lane = tid & 31, wid = tid >> 5;
    const int b = blockIdx.x;
    const uint32_t u0 = smem_u32(dsm);
    float acc[16][4];

    // common per-lane ldmatrix sub-offsets
    const int arow = ((lane >> 3) & 1) * 8 + (lane & 7);   // A row within 16-blk
    const int acol8 = (lane >> 4) * 8;                     // A col (halves)
    const int brow = (lane >> 4) * 8 + (lane & 7);         // B row within 16-blk
    const int bcol8 = ((lane >> 3) & 1) * 8;

    //======================= phase 0: scale 0 ==============================
    {
        const int wcp = wid >> 2, r0 = (wid & 3) * 32;
        char* pAh = dsm; char* pAl = dsm + 34816;
        char* pBh = dsm + 69632; char* pBl = dsm + 88064;
        const uint32_t uAh = u0, uAl = u0 + 34816, uBh = u0 + 69632, uBl = u0 + 88064;
        const uint32_t aoff = (uint32_t)((r0 + arow) * 136 + acol8) * 2;
        const uint32_t boff = (uint32_t)(brow * 72 + bcol8) * 2;
        if (tid < 128) { s_b1[tid] = b0a[tid]; s_b2[tid] = b0b[tid]; }

        const float4* xb = (const float4*)(x + (long long)b * 16384);
        float sm = 0.f, sq = 0.f;
#pragma unroll
        for (int q = 0; q < 16; q++) {
            float4 v = xb[q * 256 + tid];
            sm += v.x + v.y + v.z + v.w;
            sq += v.x * v.x + v.y * v.y + v.z * v.z + v.w * v.w;
        }
#pragma unroll
        for (int o = 16; o > 0; o >>= 1) {
            sm += __shfl_down_sync(~0u, sm, o); sq += __shfl_down_sync(~0u, sq, o);
        }
        if (lane == 0) { s_s[wid] = sm; s_q[wid] = sq; }
        __syncthreads();
        if (tid == 0) {
            float S = 0.f, Q = 0.f;
#pragma unroll
            for (int i = 0; i < 8; i++) { S += s_s[i]; Q += s_q[i]; }
            float mu = S * (1.f / 16384.f);
            s_ms[0] = mu; s_ms[1] = rsqrtf(Q * (1.f / 16384.f) - mu * mu + 1e-5f);
        }
        __syncthreads();
        const float mu = s_ms[0], rs = s_ms[1];
#pragma unroll
        for (int qq = 0; qq < 16; qq++) {
            int q = qq * 256 + tid;
            int r = q >> 5, col = (q & 31) * 4;
            float4 v = xb[q];
            float4 g = *(const float4*)(lg + r * 128 + col);
            float4 be = *(const float4*)(lb + r * 128 + col);
            v.x = (v.x - mu) * rs * g.x + be.x; v.y = (v.y - mu) * rs * g.y + be.y;
            v.z = (v.z - mu) * rs * g.z + be.z; v.w = (v.w - mu) * rs * g.w + be.w;
            split4(pAh, pAl, (uint32_t)(r * 136 + col) * 2, v);
        }

        // GEMM1: tril W0a. chunk0 = all 128 rows; chunk1 (k>=64) = rows 64..127
        zacc<16>(acc);
        load_b<128, 64, 72>(pBh, pBl, g_B0ah, g_B0al, 128, 0, tid);
        __syncthreads();
        mma_chunk<4, 2, 4, 2, 136, 72, true>(uAh, uAl, uBh, uBl, aoff, boff, wcp, 0, acc);
        __syncthreads();
        load_b<64, 64, 72>(pBh + 9216, pBl + 9216, g_B0ah + 64 * 128, g_B0al + 64 * 128,
                           128, 64, tid);
        __syncthreads();
        mma_chunk<4, 2, 4, 2, 136, 72, true>(uAh, uAl, uBh, uBl, aoff, boff, wcp, 4, acc);
        __syncthreads();
        epi<2, 4, 2, true>(acc, s_b1, r0, wcp, lane,
            [&](int r, int c, float v) { store_h(pAh, pAl, r * 136 + c, v); });

        // GEMM2: tril W0b
        zacc<16>(acc);
        load_b<128, 64, 72>(pBh, pBl, g_B0bh, g_B0bl, 128, 0, tid);
        __syncthreads();
        mma_chunk<4, 2, 4, 2, 136, 72, true>(uAh, uAl, uBh, uBl, aoff, boff, wcp, 0, acc);
        __syncthreads();
        load_b<64, 64, 72>(pBh + 9216, pBl + 9216, g_B0bh + 64 * 128, g_B0bl + 64 * 128,
                           128, 64, tid);
        __syncthreads();
        mma_chunk<4, 2, 4, 2, 136, 72, true>(uAh, uAl, uBh, uBl, aoff, boff, wcp, 4, acc);
        float* ob = out + (long long)b * 28672;
        epi<2, 4, 2, false>(acc, s_b2, r0, wcp, lane,
            [&](int r, int c, float v) { ob[c * 128 + r] = v; });
    }

    //======================= phase 1: scale 1 ==============================
    {
        __syncthreads();   // phase0 smem reads done before restaging
        const int r0c = (wid & 1) * 32, wcpc = wid >> 1;
        const int r0t = (wid & 3) * 32, wcpt = wid >> 2;
        char* pCh = dsm;          char* pCl = dsm + 33792;
        char* pA2h = dsm;         char* pA2l = dsm + 18432;
        char* pA3h = dsm + 36864; char* pA3l = dsm + 55296;
        char* pBh = dsm + 73728;  char* pBl = dsm + 92160;
        const uint32_t uCh = u0, uCl = u0 + 33792;
        const uint32_t uA2h = u0, uA2l = u0 + 18432;
        const uint32_t uA3h = u0 + 36864, uA3l = u0 + 55296;
        const uint32_t uBh = u0 + 73728, uBl = u0 + 92160;
        const uint32_t aoffc = (uint32_t)((r0c + arow) * 264 + acol8) * 2;
        const uint32_t aofft = (uint32_t)((r0t + arow) * 72 + acol8) * 2;
        const uint32_t boff = (uint32_t)(brow * 72 + bcol8) * 2;
        if (tid < 128) s_b1[tid] = c1b[tid];
        if (tid < 64) { s_b2[tid] = b1a[tid]; s_b3[tid] = b1b[tid]; }

        const float4* xb = (const float4*)(x + (long long)b * 16384);
#pragma unroll
        for (int qq = 0; qq < 16; qq++) {
            int q = qq * 256 + tid;
            int r = q >> 6, col = (q & 63) * 4;
            split4(pCh, pCl, (uint32_t)(r * 264 + col) * 2, xb[q]);
        }

        zacc<8>(acc);
#pragma unroll 1
        for (int c = 0; c < 4; c++) {
            load_b<128, 64, 72>(pBh, pBl, g_Bc1h, g_Bc1l, 256, c * 64, tid);
            __syncthreads();
            mma_chunk<4, 2, 2, 4, 264, 72, false>(uCh, uCl, uBh, uBl, aoffc, boff, wcpc,
                                                  c * 4, acc);  // A resident: ks0=c*4
            __syncthreads();
        }
        epi<2, 2, 4, false>(acc, s_b1, r0c, wcpc, lane,
            [&](int r, int c, float v) { store_h(pA2h, pA2l, c * 72 + r, v); });

        zacc<8>(acc);
        load_b<64, 64, 72>(pBh, pBl, g_B1ah, g_B1al, 64, 0, tid);
        __syncthreads();
        mma_chunk<4, 2, 2, 2, 72, 72, true>(uA2h, uA2l, uBh, uBl, aofft, boff, wcpt, 0, acc);
        __syncthreads();
        epi<2, 2, 2, true>(acc, s_b2, r0t, wcpt, lane,
            [&](int r, int c, float v) { store_h(pA3h, pA3l, r * 72 + c, v); });

        zacc<8>(acc);
        load_b<64, 64, 72>(pBh, pBl, g_B1bh, g_B1bl, 64, 0, tid);
        __syncthreads();
        mma_chunk<4, 2, 2, 2, 72, 72, true>(uA3h, uA3l, uBh, uBl, aofft, boff, wcpt, 0, acc);
        float* ob = out + (long long)b * 28672 + 16384;
        epi<2, 2, 2, false>(acc, s_b3, r0t, wcpt, lane,
            [&](int r, int c, float v) { ob[c * 128 + r] = v; });
    }

    //======================= phase 2: scale 2 ==============================
    {
        __syncthreads();   // phase1 smem reads done before restaging
        // layout: A-full 32x520 hi 0 / lo 33280 (66560); B chunk hi 66560 /
        // lo 84992 (ends 103424). After conv: A2 hi 0 / lo 10240; A3 hi 20480 /
        // lo 30720; triB hi 40960 / lo 43520 (all alias dead A-full region).
        const int r0c = (wid & 1) * 16, wcpc = wid >> 1;   // conv: M=32
        const int r0t = wid * 16;                          // triu: M=128
        char* pFAh = dsm;          char* pFAl = dsm + 33280;
        char* pCBh = dsm + 66560;  char* pCBl = dsm + 84992;
        char* pA2h = dsm;          char* pA2l = dsm + 10240;
        char* pA3h = dsm + 20480;  char* pA3l = dsm + 30720;
        char* pTBh = dsm + 40960;  char* pTBl = dsm + 43520;
        const uint32_t uFAh = u0, uFAl = u0 + 33280;
        const uint32_t uCBh = u0 + 66560, uCBl = u0 + 84992;
        const uint32_t uA2h = u0, uA2l = u0 + 10240;
        const uint32_t uA3h = u0 + 20480, uA3l = u0 + 30720;
        const uint32_t uTBh = u0 + 40960, uTBl = u0 + 43520;
        const uint32_t aoffc = (uint32_t)((r0c + arow) * 520 + acol8) * 2;
        const uint32_t aofft = (uint32_t)((r0t + arow) * 40 + acol8) * 2;
        const uint32_t boffc = (uint32_t)(brow * 72 + bcol8) * 2;
        const uint32_t bofft = (uint32_t)(brow * 40 + bcol8) * 2;
        if (tid < 128) s_b1[tid] = c2b[tid];
        if (tid < 32) { s_b2[tid] = b2a[tid]; s_b3[tid] = b2b[tid]; }

        // stage full conv A: 32 rows (s) x 512 k, stride 520
        const float* xb = x + (long long)b * 16384;
#pragma unroll
        for (int qq = 0; qq < 16; qq++) {
            int q = qq * 256 + tid;
            int r = q >> 7, col4 = (q & 127) * 4;
            float4 v = *(const float4*)(xb + r * 512 + col4);
            split4(pFAh, pFAl, (uint32_t)(r * 520 + col4) * 2, v);
        }

        zacc<4>(acc);
#pragma unroll 1
        for (int c = 0; c < 8; c++) {
            load_b<128, 64, 72>(pCBh, pCBl, g_Bc2h, g_Bc2l, 512, c * 64, tid);
            __syncthreads();
            mma_chunk<4, 1, 2, 4, 520, 72, false>(uFAh, uFAl, uCBh, uCBl, aoffc, boffc,
                                                  wcpc, c * 4, acc);  // A resident
            __syncthreads();
        }
        // conv + bias -> A2: row = co (stride 40), col = s
        epi<1, 2, 4, false>(acc, s_b1, r0c, wcpc, lane,
            [&](int r, int c, float v) { store_h(pA2h, pA2l, c * 40 + r, v); });

        zacc<4>(acc);
        load_b<32, 32, 40>(pTBh, pTBl, g_B2ah, g_B2al, 32, 0, tid);
        __syncthreads();
        mma_chunk<2, 1, 2, 1, 40, 40, true>(uA2h, uA2l, uTBh, uTBl, aofft, bofft, 0, 0, acc);
        __syncthreads();
        epi<1, 2, 1, true>(acc, s_b2, r0t, 0, lane,
            [&](int r, int c, float v) { store_h(pA3h, pA3l, r * 40 + c, v); });

        zacc<4>(acc);
        load_b<32, 32, 40>(pTBh, pTBl, g_B2bh, g_B2bl, 32, 0, tid);
        __syncthreads();
        mma_chunk<2, 1, 2, 1, 40, 40, true>(uA3h, uA3l, uTBh, uTBl, aofft, bofft, 0, 0, acc);
        float* ob = out + (long long)b * 28672 + 24576;
        epi<1, 2, 1, false>(acc, s_b3, r0t, 0, lane,
            [&](int r, int c, float v) { ob[c * 128 + r] = v; });
    }
}

// ---------------------------------------------------------------------------
extern "C" void kernel_launch(void* const* d_in, const int* in_sizes, int n_in,
                              void* d_out, int out_size) {
    const float* x   = (const float*)d_in[0];
    const float* lg  = (const float*)d_in[1];
    const float* lb  = (const float*)d_in[2];
    const float* W0a = (const float*)d_in[3];
    const float* b0a = (const float*)d_in[4];
    const float* W0b = (const float*)d_in[5];
    const float* b0b = (const float*)d_in[6];
    const float* c1w = (const float*)d_in[7];
    const float* c1b = (const float*)d_in[8];
    const float* W1a = (const float*)d_in[9];
    const float* b1a = (const float*)d_in[10];
    const float* W1b = (const float*)d_in[11];
    const float* b1b = (const float*)d_in[12];
    const float* c2w = (const float*)d_in[13];
    const float* c2b = (const float*)d_in[14];
    const float* W2a = (const float*)d_in[15];
    const float* b2a = (const float*)d_in[16];
    const float* W2b = (const float*)d_in[17];
    const float* b2b = (const float*)d_in[18];
    float* out = (float*)d_out;

    const int ds = 110592;
    cudaFuncSetAttribute(mega_kernel, cudaFuncAttributeMaxDynamicSharedMemorySize, ds);

    prep_k<<<128, 256>>>(W0a, W0b, W1a, W1b, W2a, W2b, c1w, c2w);
    mega_kernel<<<2048, 256, ds>>>(x, lg, lb, b0a, b0b, c1b, b1a, b1b,
                                   c2b, b2a, b2b, out);
}